// round 6
// baseline (speedup 1.0000x reference)
#include <cuda_runtime.h>
#include <cstdint>

#define DDIM 64
#define KCODES 1024
#define NTOK 131072
#define TM 128
#define NTHREADS 256
#define NCHUNKS 16
#define CCHUNK 64
#define CAP 6
#define MARGIN 0.008f

#define ROWW 72                         // words per fragment row (288B, bank-safe)
#define CHUNK_BYTES (CCHUNK * ROWW * 4) // 18432

// ---------------- smem layout (bytes) ----------------
#define OFF_XF   0                      // float [128][65] = 33280
#define OFF_CN   33280                  // float [1024]    = 4096
#define OFF_CAND 37376                  // int [128][4][6] = 12288
#define OFF_XNS  49664                  // float [128]
#define OFF_WIX  50176                  // int [128]
#define OFF_OFL  50688                  // int [128]
#define OFF_B    51200                  // 3 x 18432 = 55296
#define SMEM_BYTES (OFF_B + 3 * CHUNK_BYTES)   // 106496

__device__ float g_cn[KCODES];
__device__ __align__(256) uint32_t g_bT[KCODES * ROWW];  // tf32, fragment order

__device__ __forceinline__ uint32_t f2tf(float x) {
    uint32_t r;
    asm("cvt.rna.tf32.f32 %0, %1;" : "=r"(r) : "f"(x));
    return r;
}

// prep: ||c||^2 (exact seq order) + fragment-ordered tf32 codebook (R5-verified)
__global__ void vq_prep(const float* __restrict__ cb) {
    int r = blockIdx.x * blockDim.x + threadIdx.x;
    if (r >= KCODES) return;
    const float* cr = cb + r * DDIM;
    float acc = 0.f;
#pragma unroll
    for (int d = 0; d < DDIM; d++) acc = __fadd_rn(acc, __fmul_rn(cr[d], cr[d]));
    g_cn[r] = acc;
    const int qoff[4] = {0, 16, 36, 52};
#pragma unroll
    for (int q = 0; q < 4; q++)
#pragma unroll
        for (int kc = 0; kc < 8; kc++) {
            g_bT[r * ROWW + qoff[q] + kc * 2 + 0] = f2tf(cr[kc * 8 + q]);
            g_bT[r * ROWW + qoff[q] + kc * 2 + 1] = f2tf(cr[kc * 8 + q + 4]);
        }
#pragma unroll
    for (int p = 68; p < 72; p++) g_bT[r * ROWW + p] = 0;
}

__device__ __forceinline__ void mma_tf32(float* c, const uint32_t* a,
                                         uint32_t b0, uint32_t b1) {
    asm volatile(
        "mma.sync.aligned.m16n8k8.row.col.f32.tf32.tf32.f32 "
        "{%0,%1,%2,%3}, {%4,%5,%6,%7}, {%8,%9}, {%0,%1,%2,%3};"
        : "+f"(c[0]), "+f"(c[1]), "+f"(c[2]), "+f"(c[3])
        : "r"(a[0]), "r"(a[1]), "r"(a[2]), "r"(a[3]), "r"(b0), "r"(b1));
}
__device__ __forceinline__ uint4 lds128(uint32_t a) {
    uint4 v;
    asm volatile("ld.shared.v4.u32 {%0,%1,%2,%3}, [%4];"
                 : "=r"(v.x), "=r"(v.y), "=r"(v.z), "=r"(v.w) : "r"(a));
    return v;
}
__device__ __forceinline__ uint32_t smem_u32(const void* p) {
    uint32_t a;
    asm("{ .reg .u64 t; cvta.to.shared.u64 t, %1; cvt.u32.u64 %0, t; }" : "=r"(a) : "l"(p));
    return a;
}
__device__ __forceinline__ void issue_chunk(uint32_t dst, const char* src) {
#pragma unroll
    for (int k = 0; k < 5; k++) {
        int off = (threadIdx.x + k * NTHREADS) * 16;
        if (off < CHUNK_BYTES)
            asm volatile("cp.async.ca.shared.global [%0], [%1], 16;"
                         :: "r"(dst + off), "l"(src + off) : "memory");
    }
    asm volatile("cp.async.commit_group;" ::: "memory");
}

// exact rescore: bit-matches reference (R2/R4/R5-verified)
__device__ __forceinline__ float exact_d2(const float* __restrict__ cb,
                                          const float* __restrict__ xrow,
                                          float xn, float cnk, int k) {
    const float4* cr = (const float4*)(cb + k * DDIM);
    float s = 0.f;
#pragma unroll
    for (int i = 0; i < 16; i++) {
        float4 v = cr[i];
        s = __fmaf_rn(xrow[4 * i + 0], v.x, s);
        s = __fmaf_rn(xrow[4 * i + 1], v.y, s);
        s = __fmaf_rn(xrow[4 * i + 2], v.z, s);
        s = __fmaf_rn(xrow[4 * i + 3], v.w, s);
    }
    return __fadd_rn(__fsub_rn(xn, __fmul_rn(2.0f, s)), cnk);
}

__global__ __launch_bounds__(NTHREADS, 2)
void vq_main(const float* __restrict__ h, const float* __restrict__ cb,
             float* __restrict__ outZ, float* __restrict__ outQ) {
    extern __shared__ char smem[];
    float* Xf   = (float*)(smem + OFF_XF);
    float* Cn   = (float*)(smem + OFF_CN);
    int*   cand = (int*)(smem + OFF_CAND);
    float* xns  = (float*)(smem + OFF_XNS);
    int*   wix  = (int*)(smem + OFF_WIX);
    int*   ofl  = (int*)(smem + OFF_OFL);
    const uint32_t sbase = smem_u32(smem);

    const int tid = threadIdx.x;
    const int wid = tid >> 5;
    const int lid = tid & 31;
    const int g = lid >> 2;
    const int q = lid & 3;
    const int tw = wid * 16;           // 8 warps x 16 tokens = 128
    const int n0 = blockIdx.x * TM;
    const int b = n0 >> 12;
    const long base = (long)b * 262144 + (n0 & 4095);

    // prefetch B chunks 0..2 (overlaps with everything below)
#pragma unroll
    for (int c = 0; c < 3; c++)
        issue_chunk(sbase + OFF_B + c * CHUNK_BYTES, (const char*)g_bT + c * CHUNK_BYTES);

    // Xf exact fp32 tile (coalesced d-major)
    for (int i = tid; i < 64 * 32; i += NTHREADS) {
        int d = i >> 5, t4 = i & 31;
        float4 v = *(const float4*)(h + base + (long)d * 4096 + t4 * 4);
        Xf[(t4 * 4 + 0) * 65 + d] = v.x;
        Xf[(t4 * 4 + 1) * 65 + d] = v.y;
        Xf[(t4 * 4 + 2) * 65 + d] = v.z;
        Xf[(t4 * 4 + 3) * 65 + d] = v.w;
    }
    for (int i = tid; i < KCODES; i += NTHREADS) Cn[i] = g_cn[i];
    if (tid < 128) ofl[tid] = 0;
    __syncthreads();

    // exact xn (sequential mul-then-add, reference order)
    if (tid < 128) {
        float acc = 0.f;
#pragma unroll
        for (int d = 0; d < 64; d++) {
            float xv = Xf[tid * 65 + d];
            acc = __fadd_rn(acc, __fmul_rn(xv, xv));
        }
        xns[tid] = acc;
    }

    // A fragments (16 tokens, m16n8k8 row-major; layout verified R4)
    uint32_t afr[32];
    {
        const float* xr = &Xf[(tw + g) * 65];
#pragma unroll
        for (int kc = 0; kc < 8; kc++) {
            int d0 = kc * 8 + q;
            afr[kc * 4 + 0] = f2tf(xr[d0]);
            afr[kc * 4 + 1] = f2tf(xr[8 * 65 + d0]);
            afr[kc * 4 + 2] = f2tf(xr[d0 + 4]);
            afr[kc * 4 + 3] = f2tf(xr[8 * 65 + d0 + 4]);
        }
    }
    __syncthreads();

    const int tok0 = tw + g, tok1 = tw + g + 8;
    const float xn0 = xns[tok0], xn1 = xns[tok1];
    float best0 = 3.4e38f, best1 = 3.4e38f;
    int cnt0 = 0, cnt1 = 0;
    const uint32_t qoffB = (uint32_t)(q * 64 + (q >> 1) * 16);  // {0,64,144,208} bytes

#pragma unroll 1
    for (int c = 0; c < NCHUNKS; c++) {
        asm volatile("cp.async.wait_group 2;" ::: "memory");
        __syncthreads();

        const uint32_t bb = sbase + OFF_B + (c % 3) * CHUNK_BYTES;
        const int cbase = c * CCHUNK;

        float acc[8][4];
#pragma unroll
        for (int j = 0; j < 8; j++) {
#pragma unroll
            for (int e = 0; e < 4; e++) acc[j][e] = 0.f;
            uint32_t a = bb + (uint32_t)((j * 8 + g) * 288) + qoffB;
            uint4 v0 = lds128(a);
            uint4 v1 = lds128(a + 16);
            uint4 v2 = lds128(a + 32);
            uint4 v3 = lds128(a + 48);
            mma_tf32(acc[j], afr + 0,  v0.x, v0.y);
            mma_tf32(acc[j], afr + 4,  v0.z, v0.w);
            mma_tf32(acc[j], afr + 8,  v1.x, v1.y);
            mma_tf32(acc[j], afr + 12, v1.z, v1.w);
            mma_tf32(acc[j], afr + 16, v2.x, v2.y);
            mma_tf32(acc[j], afr + 20, v2.z, v2.w);
            mma_tf32(acc[j], afr + 24, v3.x, v3.y);
            mma_tf32(acc[j], afr + 28, v3.z, v3.w);
        }

        // epilogue: approx d2, candidate collection
#pragma unroll
        for (int j = 0; j < 8; j++) {
            int k0 = cbase + j * 8 + q * 2;
            float2 cn2 = *(const float2*)&Cn[k0];
            float a00 = xn0 - 2.0f * acc[j][0] + cn2.x;
            float a01 = xn0 - 2.0f * acc[j][1] + cn2.y;
            float a10 = xn1 - 2.0f * acc[j][2] + cn2.x;
            float a11 = xn1 - 2.0f * acc[j][3] + cn2.y;
            if (fminf(a00, a01) < best0 + MARGIN) {
                if (a00 < best0 + MARGIN) {
                    if (cnt0 < CAP) cand[(tok0 * 4 + q) * CAP + cnt0] = k0; else ofl[tok0] = 1;
                    cnt0++;
                }
                if (a01 < best0 + MARGIN) {
                    if (cnt0 < CAP) cand[(tok0 * 4 + q) * CAP + cnt0] = k0 + 1; else ofl[tok0] = 1;
                    cnt0++;
                }
                best0 = fminf(best0, fminf(a00, a01));
            }
            if (fminf(a10, a11) < best1 + MARGIN) {
                if (a10 < best1 + MARGIN) {
                    if (cnt1 < CAP) cand[(tok1 * 4 + q) * CAP + cnt1] = k0; else ofl[tok1] = 1;
                    cnt1++;
                }
                if (a11 < best1 + MARGIN) {
                    if (cnt1 < CAP) cand[(tok1 * 4 + q) * CAP + cnt1] = k0 + 1; else ofl[tok1] = 1;
                    cnt1++;
                }
                best1 = fminf(best1, fminf(a10, a11));
            }
        }
        // tighten bests across the quad
        best0 = fminf(best0, __shfl_xor_sync(0xffffffffu, best0, 1));
        best0 = fminf(best0, __shfl_xor_sync(0xffffffffu, best0, 2));
        best1 = fminf(best1, __shfl_xor_sync(0xffffffffu, best1, 1));
        best1 = fminf(best1, __shfl_xor_sync(0xffffffffu, best1, 2));

        __syncthreads();
        if (c + 3 < NCHUNKS)
            issue_chunk(sbase + OFF_B + ((c + 3) % 3) * CHUNK_BYTES,
                        (const char*)g_bT + (c + 3) * CHUNK_BYTES);
    }

    // exact rescore (bit-matches reference); quad combine, lowest-index tie-break
#pragma unroll
    for (int s = 0; s < 2; s++) {
        int t = s ? tok1 : tok0;
        int cnt = s ? cnt1 : cnt0;
        const float* xrow = &Xf[t * 65];
        float xn = s ? xn1 : xn0;
        float bv = 3.4e38f;
        int bi = 0x7fffffff;
        if (ofl[t]) {
            for (int k = q; k < KCODES; k += 4) {
                float d2 = exact_d2(cb, xrow, xn, Cn[k], k);
                if (d2 < bv || (d2 == bv && k < bi)) { bv = d2; bi = k; }
            }
        } else {
            for (int i = 0; i < cnt; i++) {
                int k = cand[(t * 4 + q) * CAP + i];
                float d2 = exact_d2(cb, xrow, xn, Cn[k], k);
                if (d2 < bv || (d2 == bv && k < bi)) { bv = d2; bi = k; }
            }
        }
#pragma unroll
        for (int off = 1; off < 4; off <<= 1) {
            float ov = __shfl_xor_sync(0xffffffffu, bv, off);
            int oi = __shfl_xor_sync(0xffffffffu, bi, off);
            if (ov < bv || (ov == bv && oi < bi)) { bv = ov; bi = oi; }
        }
        if (q == 0) {
            wix[t] = bi;
            if (outZ) outZ[n0 + t] = (float)bi;
        }
    }
    __syncthreads();

    // q gather
    if (outQ) {
        for (int i = tid; i < 128 * 16; i += NTHREADS) {
            int tt = i >> 4, c4 = i & 15;
            float4 v = *(const float4*)&cb[wix[tt] * DDIM + c4 * 4];
            *(float4*)&outQ[(long)(n0 + tt) * DDIM + c4 * 4] = v;
        }
    }
}

extern "C" void kernel_launch(void* const* d_in, const int* in_sizes, int n_in,
                              void* d_out, int out_size) {
    const float* h = (const float*)d_in[0];
    const float* cb = (const float*)d_in[1];
    float* out = (float*)d_out;

    float* outZ = nullptr;
    float* outQ = nullptr;
    if (out_size >= NTOK + NTOK * DDIM) { outZ = out; outQ = out + NTOK; }
    else if (out_size == NTOK * DDIM)   { outQ = out; }
    else                                { outZ = out; }

    cudaFuncSetAttribute(vq_main, cudaFuncAttributeMaxDynamicSharedMemorySize, SMEM_BYTES);
    vq_prep<<<4, 256>>>(cb);
    vq_main<<<NTOK / TM, NTHREADS, SMEM_BYTES>>>(h, cb, outZ, outQ);
}

// round 7
// speedup vs baseline: 1.0084x; 1.0084x over previous
#include <cuda_runtime.h>
#include <cstdint>

#define DDIM 64
#define KCODES 1024
#define NTOK 131072
#define TM 128
#define NTHREADS 256
#define NCHUNKS 16
#define CCHUNK 64
#define CAP 6
#define MARGIN 0.008f

#define ROWW 72                         // words per fragment row (288B, bank-safe)
#define CHUNK_BYTES (CCHUNK * ROWW * 4) // 18432

// ---------------- smem layout (bytes) ----------------
#define OFF_XF   0                      // float [128][65] = 33280
#define OFF_CN   33280                  // float [1024]    = 4096
#define OFF_CAND 37376                  // int [128][4][6] = 12288
#define OFF_XNS  49664                  // float [128]
#define OFF_WIX  50176                  // int [128]
#define OFF_OFL  50688                  // int [128]
#define OFF_B    51200                  // 3 x 18432
#define SMEM_BYTES (OFF_B + 3 * CHUNK_BYTES)   // 106496

__device__ float g_cn[KCODES];
__device__ __align__(256) uint32_t g_bT[KCODES * ROWW];  // tf32, fragment order (R5/R6-verified)

__device__ __forceinline__ uint32_t f2tf(float x) {
    uint32_t r;
    asm("cvt.rna.tf32.f32 %0, %1;" : "=r"(r) : "f"(x));
    return r;
}

__global__ void vq_prep(const float* __restrict__ cb) {
    int r = blockIdx.x * blockDim.x + threadIdx.x;
    if (r >= KCODES) return;
    const float* cr = cb + r * DDIM;
    float acc = 0.f;
#pragma unroll
    for (int d = 0; d < DDIM; d++) acc = __fadd_rn(acc, __fmul_rn(cr[d], cr[d]));
    g_cn[r] = acc;
    const int qoff[4] = {0, 16, 36, 52};
#pragma unroll
    for (int q = 0; q < 4; q++)
#pragma unroll
        for (int kc = 0; kc < 8; kc++) {
            g_bT[r * ROWW + qoff[q] + kc * 2 + 0] = f2tf(cr[kc * 8 + q]);
            g_bT[r * ROWW + qoff[q] + kc * 2 + 1] = f2tf(cr[kc * 8 + q + 4]);
        }
#pragma unroll
    for (int p = 68; p < 72; p++) g_bT[r * ROWW + p] = 0;
}

__device__ __forceinline__ void mma_tf32(float* c, const uint32_t* a,
                                         uint32_t b0, uint32_t b1) {
    asm volatile(
        "mma.sync.aligned.m16n8k8.row.col.f32.tf32.tf32.f32 "
        "{%0,%1,%2,%3}, {%4,%5,%6,%7}, {%8,%9}, {%0,%1,%2,%3};"
        : "+f"(c[0]), "+f"(c[1]), "+f"(c[2]), "+f"(c[3])
        : "r"(a[0]), "r"(a[1]), "r"(a[2]), "r"(a[3]), "r"(b0), "r"(b1));
}
__device__ __forceinline__ uint4 lds128(uint32_t a) {
    uint4 v;
    asm volatile("ld.shared.v4.u32 {%0,%1,%2,%3}, [%4];"
                 : "=r"(v.x), "=r"(v.y), "=r"(v.z), "=r"(v.w) : "r"(a));
    return v;
}
__device__ __forceinline__ uint32_t smem_u32(const void* p) {
    uint32_t a;
    asm("{ .reg .u64 t; cvta.to.shared.u64 t, %1; cvt.u32.u64 %0, t; }" : "=r"(a) : "l"(p));
    return a;
}
__device__ __forceinline__ void issue_chunk(uint32_t dst, const char* src) {
#pragma unroll
    for (int k = 0; k < 5; k++) {
        int off = (threadIdx.x + k * NTHREADS) * 16;
        if (off < CHUNK_BYTES)
            asm volatile("cp.async.ca.shared.global [%0], [%1], 16;"
                         :: "r"(dst + off), "l"(src + off) : "memory");
    }
    asm volatile("cp.async.commit_group;" ::: "memory");
}

// exact rescore: bit-matches reference (R2/R4/R5/R6-verified)
__device__ __forceinline__ float exact_d2(const float* __restrict__ cb,
                                          const float* __restrict__ xrow,
                                          float xn, float cnk, int k) {
    const float4* cr = (const float4*)(cb + k * DDIM);
    float s = 0.f;
#pragma unroll
    for (int i = 0; i < 16; i++) {
        float4 v = cr[i];
        s = __fmaf_rn(xrow[4 * i + 0], v.x, s);
        s = __fmaf_rn(xrow[4 * i + 1], v.y, s);
        s = __fmaf_rn(xrow[4 * i + 2], v.z, s);
        s = __fmaf_rn(xrow[4 * i + 3], v.w, s);
    }
    return __fadd_rn(__fsub_rn(xn, __fmul_rn(2.0f, s)), cnk);
}

__global__ __launch_bounds__(NTHREADS, 2)
void vq_main(const float* __restrict__ h, const float* __restrict__ cb,
             float* __restrict__ outZ, float* __restrict__ outQ) {
    extern __shared__ char smem[];
    float* Xf   = (float*)(smem + OFF_XF);
    float* Cn   = (float*)(smem + OFF_CN);
    int*   cand = (int*)(smem + OFF_CAND);
    float* xns  = (float*)(smem + OFF_XNS);
    int*   wix  = (int*)(smem + OFF_WIX);
    int*   ofl  = (int*)(smem + OFF_OFL);
    const uint32_t sbase = smem_u32(smem);

    const int tid = threadIdx.x;
    const int wid = tid >> 5;
    const int lid = tid & 31;
    const int g = lid >> 2;
    const int q = lid & 3;
    const int tw = wid * 16;
    const int n0 = blockIdx.x * TM;
    const int b = n0 >> 12;
    const long base = (long)b * 262144 + (n0 & 4095);

#pragma unroll
    for (int c = 0; c < 3; c++)
        issue_chunk(sbase + OFF_B + c * CHUNK_BYTES, (const char*)g_bT + c * CHUNK_BYTES);

    for (int i = tid; i < 64 * 32; i += NTHREADS) {
        int d = i >> 5, t4 = i & 31;
        float4 v = *(const float4*)(h + base + (long)d * 4096 + t4 * 4);
        Xf[(t4 * 4 + 0) * 65 + d] = v.x;
        Xf[(t4 * 4 + 1) * 65 + d] = v.y;
        Xf[(t4 * 4 + 2) * 65 + d] = v.z;
        Xf[(t4 * 4 + 3) * 65 + d] = v.w;
    }
    for (int i = tid; i < KCODES; i += NTHREADS) Cn[i] = g_cn[i];
    if (tid < 128) ofl[tid] = 0;
    __syncthreads();

    if (tid < 128) {
        float acc = 0.f;
#pragma unroll
        for (int d = 0; d < 64; d++) {
            float xv = Xf[tid * 65 + d];
            acc = __fadd_rn(acc, __fmul_rn(xv, xv));
        }
        xns[tid] = acc;
    }

    uint32_t afr[32];
    {
        const float* xr = &Xf[(tw + g) * 65];
#pragma unroll
        for (int kc = 0; kc < 8; kc++) {
            int d0 = kc * 8 + q;
            afr[kc * 4 + 0] = f2tf(xr[d0]);
            afr[kc * 4 + 1] = f2tf(xr[8 * 65 + d0]);
            afr[kc * 4 + 2] = f2tf(xr[d0 + 4]);
            afr[kc * 4 + 3] = f2tf(xr[8 * 65 + d0 + 4]);
        }
    }
    __syncthreads();

    const int tok0 = tw + g, tok1 = tw + g + 8;
    const float xn0 = xns[tok0], xn1 = xns[tok1];
    float best0 = 3.4e38f, best1 = 3.4e38f;
    int cnt0 = 0, cnt1 = 0;
    const uint32_t qoffB = (uint32_t)(q * 64 + (q >> 1) * 16);

#pragma unroll 1
    for (int c = 0; c < NCHUNKS; c++) {
        // tail-correct pipeline wait: pending allowed = (#issued) - (c+1)
        if (c < 14)      asm volatile("cp.async.wait_group 2;" ::: "memory");
        else if (c == 14) asm volatile("cp.async.wait_group 1;" ::: "memory");
        else              asm volatile("cp.async.wait_group 0;" ::: "memory");
        __syncthreads();

        const uint32_t bb = sbase + OFF_B + (c % 3) * CHUNK_BYTES;
        const int cbase = c * CCHUNK;

        // j-pairs: only 2 accumulators (8 regs) live at once; epilogue inline
#pragma unroll
        for (int jp = 0; jp < 4; jp++) {
            const int j0 = jp * 2, j1 = jp * 2 + 1;
            uint32_t a0 = bb + (uint32_t)((j0 * 8 + g) * 288) + qoffB;
            uint32_t a1 = a0 + 8 * 288;

            float ac0[4] = {0.f, 0.f, 0.f, 0.f};
            float ac1[4] = {0.f, 0.f, 0.f, 0.f};
            uint4 v0, v1;
            v0 = lds128(a0);
            v1 = lds128(a1);
            mma_tf32(ac0, afr + 0,  v0.x, v0.y);
            mma_tf32(ac1, afr + 0,  v1.x, v1.y);
            mma_tf32(ac0, afr + 4,  v0.z, v0.w);
            mma_tf32(ac1, afr + 4,  v1.z, v1.w);
            v0 = lds128(a0 + 16);
            v1 = lds128(a1 + 16);
            mma_tf32(ac0, afr + 8,  v0.x, v0.y);
            mma_tf32(ac1, afr + 8,  v1.x, v1.y);
            mma_tf32(ac0, afr + 12, v0.z, v0.w);
            mma_tf32(ac1, afr + 12, v1.z, v1.w);
            v0 = lds128(a0 + 32);
            v1 = lds128(a1 + 32);
            mma_tf32(ac0, afr + 16, v0.x, v0.y);
            mma_tf32(ac1, afr + 16, v1.x, v1.y);
            mma_tf32(ac0, afr + 20, v0.z, v0.w);
            mma_tf32(ac1, afr + 20, v1.z, v1.w);
            v0 = lds128(a0 + 48);
            v1 = lds128(a1 + 48);
            mma_tf32(ac0, afr + 24, v0.x, v0.y);
            mma_tf32(ac1, afr + 24, v1.x, v1.y);
            mma_tf32(ac0, afr + 28, v0.z, v0.w);
            mma_tf32(ac1, afr + 28, v1.z, v1.w);

            // inline epilogue for j0 and j1 (frees accumulators immediately)
#pragma unroll
            for (int s = 0; s < 2; s++) {
                const float* ac = s ? ac1 : ac0;
                int k0 = cbase + (s ? j1 : j0) * 8 + q * 2;
                float2 cn2 = *(const float2*)&Cn[k0];
                float a00 = xn0 - 2.0f * ac[0] + cn2.x;
                float a01 = xn0 - 2.0f * ac[1] + cn2.y;
                float a10 = xn1 - 2.0f * ac[2] + cn2.x;
                float a11 = xn1 - 2.0f * ac[3] + cn2.y;
                if (fminf(a00, a01) < best0 + MARGIN) {
                    if (a00 < best0 + MARGIN) {
                        if (cnt0 < CAP) cand[(tok0 * 4 + q) * CAP + cnt0] = k0; else ofl[tok0] = 1;
                        cnt0++;
                    }
                    if (a01 < best0 + MARGIN) {
                        if (cnt0 < CAP) cand[(tok0 * 4 + q) * CAP + cnt0] = k0 + 1; else ofl[tok0] = 1;
                        cnt0++;
                    }
                    best0 = fminf(best0, fminf(a00, a01));
                }
                if (fminf(a10, a11) < best1 + MARGIN) {
                    if (a10 < best1 + MARGIN) {
                        if (cnt1 < CAP) cand[(tok1 * 4 + q) * CAP + cnt1] = k0; else ofl[tok1] = 1;
                        cnt1++;
                    }
                    if (a11 < best1 + MARGIN) {
                        if (cnt1 < CAP) cand[(tok1 * 4 + q) * CAP + cnt1] = k0 + 1; else ofl[tok1] = 1;
                        cnt1++;
                    }
                    best1 = fminf(best1, fminf(a10, a11));
                }
            }
        }

        best0 = fminf(best0, __shfl_xor_sync(0xffffffffu, best0, 1));
        best0 = fminf(best0, __shfl_xor_sync(0xffffffffu, best0, 2));
        best1 = fminf(best1, __shfl_xor_sync(0xffffffffu, best1, 1));
        best1 = fminf(best1, __shfl_xor_sync(0xffffffffu, best1, 2));

        __syncthreads();
        if (c + 3 < NCHUNKS)
            issue_chunk(sbase + OFF_B + ((c + 3) % 3) * CHUNK_BYTES,
                        (const char*)g_bT + (c + 3) * CHUNK_BYTES);
    }

    // exact rescore (bit-matches reference); quad combine, lowest-index tie-break
#pragma unroll
    for (int s = 0; s < 2; s++) {
        int t = s ? tok1 : tok0;
        int cnt = s ? cnt1 : cnt0;
        const float* xrow = &Xf[t * 65];
        float xn = s ? xn1 : xn0;
        float bv = 3.4e38f;
        int bi = 0x7fffffff;
        if (ofl[t]) {
            for (int k = q; k < KCODES; k += 4) {
                float d2 = exact_d2(cb, xrow, xn, Cn[k], k);
                if (d2 < bv || (d2 == bv && k < bi)) { bv = d2; bi = k; }
            }
        } else {
            for (int i = 0; i < cnt; i++) {
                int k = cand[(t * 4 + q) * CAP + i];
                float d2 = exact_d2(cb, xrow, xn, Cn[k], k);
                if (d2 < bv || (d2 == bv && k < bi)) { bv = d2; bi = k; }
            }
        }
#pragma unroll
        for (int off = 1; off < 4; off <<= 1) {
            float ov = __shfl_xor_sync(0xffffffffu, bv, off);
            int oi = __shfl_xor_sync(0xffffffffu, bi, off);
            if (ov < bv || (ov == bv && oi < bi)) { bv = ov; bi = oi; }
        }
        if (q == 0) {
            wix[t] = bi;
            if (outZ) outZ[n0 + t] = (float)bi;
        }
    }
    __syncthreads();

    if (outQ) {
        for (int i = tid; i < 128 * 16; i += NTHREADS) {
            int tt = i >> 4, c4 = i & 15;
            float4 v = *(const float4*)&cb[wix[tt] * DDIM + c4 * 4];
            *(float4*)&outQ[(long)(n0 + tt) * DDIM + c4 * 4] = v;
        }
    }
}

extern "C" void kernel_launch(void* const* d_in, const int* in_sizes, int n_in,
                              void* d_out, int out_size) {
    const float* h = (const float*)d_in[0];
    const float* cb = (const float*)d_in[1];
    float* out = (float*)d_out;

    float* outZ = nullptr;
    float* outQ = nullptr;
    if (out_size >= NTOK + NTOK * DDIM) { outZ = out; outQ = out + NTOK; }
    else if (out_size == NTOK * DDIM)   { outQ = out; }
    else                                { outZ = out; }

    cudaFuncSetAttribute(vq_main, cudaFuncAttributeMaxDynamicSharedMemorySize, SMEM_BYTES);
    vq_prep<<<4, 256>>>(cb);
    vq_main<<<NTOK / TM, NTHREADS, SMEM_BYTES>>>(h, cb, outZ, outQ);
}

// round 8
// speedup vs baseline: 9.6238x; 9.5433x over previous
#include <cuda_runtime.h>
#include <cstdint>

#define DDIM 64
#define KCODES 1024
#define NTOK 131072
#define TM 128
#define NTHREADS 512
#define PASSES 4
#define CPASS 256

typedef unsigned long long ull;

// ---------------- smem layout (bytes) ----------------
#define OFF_XF   0                    // float [64][128] = 32768 (d-major)
#define OFF_CS   32768                // float [64][256] = 65536 (per-pass code tile, d-major)
#define OFF_CN   98304                // float [1024]    = 4096
#define OFF_XNS  102400               // float [128]
#define OFF_WIX  102912               // int [128]
#define SMEM_BYTES 103424
// reduction overlays Cs after the last pass:
#define OFF_REDV OFF_CS               // float [16][128] = 8192
#define OFF_REDI (OFF_CS + 8192)      // int   [16][128] = 8192

__device__ float g_cn[KCODES];                     // ||c||^2 (sequential, ref order)
__device__ __align__(16) float g_cbT[DDIM * KCODES];  // transposed codebook [d][k]

__global__ void vq_prep(const float* __restrict__ cb) {
    int k = blockIdx.x * blockDim.x + threadIdx.x;
    if (k >= KCODES) return;
    float acc = 0.f;
#pragma unroll
    for (int d = 0; d < DDIM; d++) {
        float c = cb[k * DDIM + d];
        acc = __fadd_rn(acc, __fmul_rn(c, c));
        g_cbT[d * KCODES + k] = c;
    }
    g_cn[k] = acc;
}

__device__ __forceinline__ uint32_t smem_u32(const void* p) {
    uint32_t a;
    asm("{ .reg .u64 t; cvta.to.shared.u64 t, %1; cvt.u32.u64 %0, t; }" : "=r"(a) : "l"(p));
    return a;
}
__device__ __forceinline__ uint4 lds128(uint32_t a) {
    uint4 v;
    asm volatile("ld.shared.v4.u32 {%0,%1,%2,%3}, [%4];"
                 : "=r"(v.x), "=r"(v.y), "=r"(v.z), "=r"(v.w) : "r"(a));
    return v;
}
__device__ __forceinline__ void lds2u64(ull& a0, ull& a1, uint32_t a) {
    asm volatile("ld.shared.v2.b64 {%0,%1}, [%2];" : "=l"(a0), "=l"(a1) : "r"(a));
}
__device__ __forceinline__ ull rep2(uint32_t x) {
    ull r;
    asm("mov.b64 %0, {%1,%1};" : "=l"(r) : "r"(x));
    return r;
}
__device__ __forceinline__ void fma2(ull& acc, ull x, ull c) {
    asm("fma.rn.f32x2 %0, %1, %2, %0;" : "+l"(acc) : "l"(x), "l"(c));
}

__global__ __launch_bounds__(NTHREADS, 1)
void vq_main(const float* __restrict__ h, const float* __restrict__ cb,
             float* __restrict__ outZ, float* __restrict__ outQ) {
    extern __shared__ char smem[];
    float* Xf  = (float*)(smem + OFF_XF);    // [64][128]
    float* Cs  = (float*)(smem + OFF_CS);    // [64][256]
    float* Cn  = (float*)(smem + OFF_CN);
    float* xns = (float*)(smem + OFF_XNS);
    int*   wix = (int*)(smem + OFF_WIX);
    float* redv = (float*)(smem + OFF_REDV);
    int*   redi = (int*)(smem + OFF_REDI);
    const uint32_t sbase = smem_u32(smem);

    const int tid = threadIdx.x;
    const int wid = tid >> 5;
    const int l = tid & 31;
    const int n0 = blockIdx.x * TM;
    const int b = n0 >> 12;
    const long base = (long)b * 262144 + (n0 & 4095);

    // ---- Xf [d][t]: coalesced LDG.128 -> STS.128, conflict-free ----
    for (int i = tid; i < 64 * 32; i += NTHREADS) {
        int d = i >> 5, t4 = i & 31;
        *(float4*)&Xf[d * 128 + t4 * 4] =
            *(const float4*)(h + base + (long)d * 4096 + t4 * 4);
    }
    for (int i = tid; i < KCODES; i += NTHREADS) Cn[i] = g_cn[i];
    __syncthreads();

    // ---- exact xn (sequential mul-then-add; bit-matches reference, R2-verified) ----
    if (tid < 128) {
        float acc = 0.f;
#pragma unroll
        for (int d = 0; d < 64; d++) {
            float xv = Xf[d * 128 + tid];
            acc = __fadd_rn(acc, __fmul_rn(xv, xv));
        }
        xns[tid] = acc;
    }
    // build Cs for pass 0 (concurrent with xns)
    for (int i = tid; i < 64 * 64; i += NTHREADS) {
        int d = i >> 6, j4 = (i & 63) << 2;
        *(float4*)&Cs[d * 256 + j4] = *(const float4*)&g_cbT[d * 1024 + j4];
    }
    __syncthreads();

    float xnr[4];
    {
        float4 v = *(const float4*)&xns[4 * l];
        xnr[0] = v.x; xnr[1] = v.y; xnr[2] = v.z; xnr[3] = v.w;
    }
    float best[4] = {3.4e38f, 3.4e38f, 3.4e38f, 3.4e38f};
    int bidx[4] = {0, 0, 0, 0};

    const uint32_t xaddr = sbase + OFF_XF + 16u * l;      // this thread's 4 tokens
    const uint32_t caddr = sbase + OFF_CS + 64u * wid;    // this warp's 16 codes

#pragma unroll 1
    for (int p = 0; p < PASSES; p++) {
        // acc[cp][t] = {s(k=2cp), s(k=2cp+1)} for token t (FFMA2 chain from 0 = R2-exact)
        ull acc[8][4];
#pragma unroll
        for (int cp = 0; cp < 8; cp++)
#pragma unroll
            for (int t = 0; t < 4; t++) acc[cp][t] = 0ull;

#pragma unroll 2
        for (int d = 0; d < 64; d++) {
            uint4 xv = lds128(xaddr + (uint32_t)(d * 512));
            ull x0 = rep2(xv.x), x1 = rep2(xv.y), x2 = rep2(xv.z), x3 = rep2(xv.w);
            uint32_t ca = caddr + (uint32_t)(d * 1024);
#pragma unroll
            for (int cq = 0; cq < 4; cq++) {
                ull c0, c1;                     // {c_k,c_k+1} natural pairs, warp-uniform
                lds2u64(c0, c1, ca + cq * 16);
                fma2(acc[cq * 2 + 0][0], x0, c0);
                fma2(acc[cq * 2 + 0][1], x1, c0);
                fma2(acc[cq * 2 + 0][2], x2, c0);
                fma2(acc[cq * 2 + 0][3], x3, c0);
                fma2(acc[cq * 2 + 1][0], x0, c1);
                fma2(acc[cq * 2 + 1][1], x1, c1);
                fma2(acc[cq * 2 + 1][2], x2, c1);
                fma2(acc[cq * 2 + 1][3], x3, c1);
            }
        }

        // epilogue: d2 = fl(fl(xn-2s)+cn), running argmin (ascending k, strict <)
        const int kw = p * CPASS + wid * 16;
#pragma unroll
        for (int cp = 0; cp < 8; cp++) {
            int k0 = kw + cp * 2;
            float cn0 = Cn[k0], cn1 = Cn[k0 + 1];
#pragma unroll
            for (int t = 0; t < 4; t++) {
                ull a = acc[cp][t];
                float slo = __uint_as_float((unsigned)(a & 0xffffffffull));
                float shi = __uint_as_float((unsigned)(a >> 32));
                float d2a = __fadd_rn(__fsub_rn(xnr[t], 2.0f * slo), cn0);
                float d2b = __fadd_rn(__fsub_rn(xnr[t], 2.0f * shi), cn1);
                if (d2a < best[t]) { best[t] = d2a; bidx[t] = k0; }
                if (d2b < best[t]) { best[t] = d2b; bidx[t] = k0 + 1; }
            }
        }

        __syncthreads();
        if (p + 1 < PASSES) {
            for (int i = tid; i < 64 * 64; i += NTHREADS) {
                int d = i >> 6, j4 = (i & 63) << 2;
                *(float4*)&Cs[d * 256 + j4] =
                    *(const float4*)&g_cbT[d * 1024 + (p + 1) * CPASS + j4];
            }
            __syncthreads();
        }
    }

    // ---- cross-warp reduce (lexicographic: value, then lowest k) ----
#pragma unroll
    for (int t = 0; t < 4; t++) {
        redv[wid * 128 + 4 * l + t] = best[t];
        redi[wid * 128 + 4 * l + t] = bidx[t];
    }
    __syncthreads();

    if (tid < 128) {
        float bv = redv[tid];
        int bi = redi[tid];
#pragma unroll
        for (int w = 1; w < 16; w++) {
            float v = redv[w * 128 + tid];
            int i2 = redi[w * 128 + tid];
            if (v < bv || (v == bv && i2 < bi)) { bv = v; bi = i2; }
        }
        wix[tid] = bi;
        if (outZ) outZ[n0 + tid] = (float)bi;
    }
    __syncthreads();

    // ---- q gather ----
    if (outQ) {
        for (int i = tid; i < 128 * 16; i += NTHREADS) {
            int tt = i >> 4, c4 = i & 15;
            float4 v = *(const float4*)&cb[wix[tt] * DDIM + c4 * 4];
            *(float4*)&outQ[(long)(n0 + tt) * DDIM + c4 * 4] = v;
        }
    }
}

extern "C" void kernel_launch(void* const* d_in, const int* in_sizes, int n_in,
                              void* d_out, int out_size) {
    const float* h = (const float*)d_in[0];
    const float* cb = (const float*)d_in[1];
    float* out = (float*)d_out;

    float* outZ = nullptr;
    float* outQ = nullptr;
    if (out_size >= NTOK + NTOK * DDIM) { outZ = out; outQ = out + NTOK; }
    else if (out_size == NTOK * DDIM)   { outQ = out; }
    else                                { outZ = out; }

    cudaFuncSetAttribute(vq_main, cudaFuncAttributeMaxDynamicSharedMemorySize, SMEM_BYTES);
    vq_prep<<<4, 256>>>(cb);
    vq_main<<<NTOK / TM, NTHREADS, SMEM_BYTES>>>(h, cb, outZ, outQ);
}